// round 7
// baseline (speedup 1.0000x reference)
#include <cuda_runtime.h>
#include <cuda_bf16.h>
#include <cstdint>

#define T_ 4
#define B_ 16
#define C_ 384
#define N_ 1024
#define TB_STRIDE (B_*C_*N_)
#define CAP_ 48

// ---------------- scratch (device globals; no allocation) ----------------
__device__ unsigned int  g_mask[(size_t)T_*B_*N_*12];   // 3 MB: 384-bit channel mask per (t,b,n)
__device__ __nv_bfloat16 g_wqT[C_*C_];                  // wqT[c][o], bf16
__device__ float         g_wpT[C_*C_];                  // wpT[c][o], fp32

// ---------------- K0: transpose weights ----------------
__global__ void k_prep(const float* __restrict__ wq, const float* __restrict__ wp) {
    int i = blockIdx.x * blockDim.x + threadIdx.x;
    if (i < C_ * C_) {
        int o = i / C_;
        int c = i - o * C_;
        g_wqT[c * C_ + o] = __float2bfloat16(wq[i]);
        g_wpT[c * C_ + o] = wp[i];
    }
}

// ---------------- K1: fused LIF(x) + bit-pack into channel masks ----------------
__global__ void __launch_bounds__(128) k_lif_pack(const float* __restrict__ x) {
    const int n  = blockIdx.x * 128 + threadIdx.x;
    const int c0 = blockIdx.y * 64;
    const int b  = blockIdx.z;

    unsigned m[T_][2];
#pragma unroll
    for (int t = 0; t < T_; t++) { m[t][0] = 0u; m[t][1] = 0u; }

#pragma unroll
    for (int w2 = 0; w2 < 2; w2++) {
#pragma unroll 8
        for (int k = 0; k < 32; k++) {
            int c = c0 + w2 * 32 + k;
            const float* px = x + ((size_t)b * C_ + c) * N_ + n;
            float v = 0.0f;
#pragma unroll
            for (int t = 0; t < T_; t++) {
                float xt = px[(size_t)t * TB_STRIDE];
                float h = v + (xt - v) * 0.5f;   // tau = 2
                bool  s = (h >= 1.0f);           // v_th = 1
                v = s ? 0.0f : h;                // hard reset
                m[t][w2] |= (s ? 1u : 0u) << k;
            }
        }
    }

#pragma unroll
    for (int t = 0; t < T_; t++)
#pragma unroll
        for (int w2 = 0; w2 < 2; w2++)
            g_mask[(((size_t)t * B_ + b) * N_ + n) * 12 + blockIdx.y * 2 + w2] = m[t][w2];
}

// ---------------- K2: fused sparse pipeline, n-tiled, direct output ----------------
// block = (b, n-tile of 32); 192 threads; thread owns o0 = 2*tid, o0+1.
// dynamic smem layout:
//   stage  : float [4][8][384]          49152 B
//   lists  : u16   [4][32][CAP_]        12288 B
//   qmaskS : uint  [4][32][12]           6144 B
//   cnts   : int   [128]                  512 B
//   sbytes : u8    [4][384]              1536 B
#define SM_STAGE  0
#define SM_LISTS  49152
#define SM_QMASK  (49152 + 12288)
#define SM_CNTS   (SM_QMASK + 6144)
#define SM_SBYTES (SM_CNTS + 512)
#define SM_TOTAL  (SM_SBYTES + 1536)

__global__ void __launch_bounds__(192) k_main(
    const unsigned char* __restrict__ ak, const unsigned char* __restrict__ av,
    const float* __restrict__ qg, const float* __restrict__ qbeta,
    const float* __restrict__ qmean, const float* __restrict__ qvar,
    const float* __restrict__ bp,
    const float* __restrict__ pg, const float* __restrict__ pbeta,
    const float* __restrict__ pmean, const float* __restrict__ pvar,
    float* __restrict__ out)
{
    extern __shared__ unsigned char smraw[];
    float*          stage  = (float*)(smraw + SM_STAGE);            // [t][j][o]
    unsigned short* lists  = (unsigned short*)(smraw + SM_LISTS);   // [t][nl][CAP_]
    unsigned int*   qmaskS = (unsigned int*)(smraw + SM_QMASK);     // [t][nl][12]
    int*            cnts   = (int*)(smraw + SM_CNTS);               // [t*32+nl]
    unsigned char*  sbytes = (unsigned char*)(smraw + SM_SBYTES);   // [t][384]

    const int ng   = blockIdx.x & 31;
    const int b    = blockIdx.x >> 5;
    const int n0   = ng * 32;
    const int tid  = threadIdx.x;
    const int lane = tid & 31;
    const int warp = tid >> 5;
    const int o0   = 2 * tid;

    // ---- prologue: load masks for the whole tile ----
    for (int i = tid; i < T_ * 32 * 12; i += 192) {
        int t  = i / (32 * 12);
        int r  = i - t * (32 * 12);          // nl*12 + w
        qmaskS[i] = g_mask[(((size_t)t * B_ + b) * N_ + n0) * 12 + r];
    }
    __syncthreads();

    // ---- decode masks into compact lists (warp per (t,nl) pair) ----
    for (int p = warp; p < T_ * 32; p += 6) {
        const unsigned int* mw = qmaskS + p * 12;
        unsigned short* lst = lists + p * CAP_;
        int base = 0;
#pragma unroll
        for (int w = 0; w < 12; w++) {
            unsigned m = mw[w];
            if (m & (1u << lane)) {
                int pos = base + __popc(m & ((1u << lane) - 1));
                if (pos < CAP_) lst[pos] = (unsigned short)(w * 32 + lane);
            }
            base += __popc(m);
        }
        if (lane == 0) cnts[p] = base;
    }

    // ---- per-output-channel constants ----
    float qinv0 = qg[o0]     / sqrtf(qvar[o0]     + 1e-5f);
    float qinv1 = qg[o0 + 1] / sqrtf(qvar[o0 + 1] + 1e-5f);
    float qadd0 = qbeta[o0]     - qmean[o0]     * qinv0;
    float qadd1 = qbeta[o0 + 1] - qmean[o0 + 1] * qinv1;
    float pinv0 = pg[o0]     / sqrtf(pvar[o0]     + 1e-5f);
    float pinv1 = pg[o0 + 1] / sqrtf(pvar[o0 + 1] + 1e-5f);
    float padd0 = pbeta[o0]     - pmean[o0]     * pinv0;
    float padd1 = pbeta[o0 + 1] - pmean[o0 + 1] * pinv1;
    float bp0 = bp[o0], bp1 = bp[o0 + 1];
    __syncthreads();

    // ---- main loop over the 32 n's, in groups of 8 ----
    for (int g = 0; g < 4; g++) {
#pragma unroll 1
        for (int j = 0; j < 8; j++) {
            const int nl = g * 8 + j;
            const int n  = n0 + nl;

            // phase 1: sparse q accumulate
            float qa0[T_], qa1[T_];
#pragma unroll
            for (int t = 0; t < T_; t++) {
                float a0 = 0.0f, a1 = 0.0f;
                int p = t * 32 + nl;
                int K = cnts[p];
                const unsigned short* lst = lists + p * CAP_;
                if (K <= CAP_) {
                    int i = 0;
                    for (; i + 4 <= K; i += 4) {
                        int c0 = lst[i], c1 = lst[i + 1], c2 = lst[i + 2], c3 = lst[i + 3];
                        float2 f0 = __bfloat1622float2(*(const __nv_bfloat162*)(g_wqT + c0 * C_ + o0));
                        float2 f1 = __bfloat1622float2(*(const __nv_bfloat162*)(g_wqT + c1 * C_ + o0));
                        float2 f2 = __bfloat1622float2(*(const __nv_bfloat162*)(g_wqT + c2 * C_ + o0));
                        float2 f3 = __bfloat1622float2(*(const __nv_bfloat162*)(g_wqT + c3 * C_ + o0));
                        a0 += f0.x + f1.x + f2.x + f3.x;
                        a1 += f0.y + f1.y + f2.y + f3.y;
                    }
                    for (; i < K; i++) {
                        float2 f = __bfloat1622float2(*(const __nv_bfloat162*)(g_wqT + lst[i] * C_ + o0));
                        a0 += f.x; a1 += f.y;
                    }
                } else {
                    // overflow fallback: exact ffs scan of the 12 mask words
                    const unsigned int* mw = qmaskS + p * 12;
#pragma unroll
                    for (int w = 0; w < 12; w++) {
                        unsigned m = mw[w];
                        while (m) {
                            int bit = __ffs((int)m) - 1;
                            m &= m - 1;
                            float2 f = __bfloat1622float2(
                                *(const __nv_bfloat162*)(g_wqT + (w * 32 + bit) * C_ + o0));
                            a0 += f.x; a1 += f.y;
                        }
                    }
                }
                qa0[t] = a0; qa1[t] = a1;
            }

            // phase 2: q_bn -> q_lif scan -> attn AND (lazy gather)
            bool r0[T_], r1[T_];
            bool any = false;
            {
                float v0 = 0.0f, v1 = 0.0f;
#pragma unroll
                for (int t = 0; t < T_; t++) {
                    float qn0 = qa0[t] * qinv0 + qadd0;
                    float qn1 = qa1[t] * qinv1 + qadd1;
                    float h0 = v0 + (qn0 - v0) * 0.5f;
                    float h1 = v1 + (qn1 - v1) * 0.5f;
                    bool s0 = (h0 >= 1.0f);
                    bool s1 = (h1 >= 1.0f);
                    v0 = s0 ? 0.0f : h0;
                    v1 = s1 ? 0.0f : h1;
                    bool a0 = false, a1 = false;
                    if (s0) {
                        size_t idx = (((size_t)t * B_ + b) * C_ + o0) * (size_t)N_ + n;
                        a0 = (ak[idx] != 0) && (av[idx] != 0);
                    }
                    if (s1) {
                        size_t idx = (((size_t)t * B_ + b) * C_ + o0 + 1) * (size_t)N_ + n;
                        a1 = (ak[idx] != 0) && (av[idx] != 0);
                    }
                    r0[t] = a0; r1[t] = a1;
                    any |= a0 | a1;
                }
            }

            // phase 3: proj accumulate (skipped block-wide when no spike anywhere)
            float oa0[T_] = {0, 0, 0, 0}, oa1[T_] = {0, 0, 0, 0};
            int tot = __syncthreads_count(any ? 1 : 0);
            if (tot) {
#pragma unroll
                for (int t = 0; t < T_; t++) {
                    sbytes[t * C_ + o0]     = r0[t] ? 1 : 0;
                    sbytes[t * C_ + o0 + 1] = r1[t] ? 1 : 0;
                }
                __syncthreads();
#pragma unroll
                for (int t = 0; t < T_; t++) {
                    const unsigned char* sb = sbytes + t * C_;
                    for (int c = 0; c < C_; c++) {
                        if (sb[c]) {
                            float2 w = *(const float2*)(g_wpT + c * C_ + o0);
                            oa0[t] += w.x; oa1[t] += w.y;
                        }
                    }
                }
                __syncthreads();   // protect sbytes before next nl reuses it
            }

            // epilogue: bias + proj bn -> stage[t][j][o]
#pragma unroll
            for (int t = 0; t < T_; t++) {
                float2 y;
                y.x = (oa0[t] + bp0) * pinv0 + padd0;
                y.y = (oa1[t] + bp1) * pinv1 + padd1;
                *(float2*)(stage + ((t * 8 + j) * C_) + o0) = y;
            }
        }

        // flush group of 8 n: coalesced float2 rows (32B per (t,o) row = full sectors)
        __syncthreads();
        for (int q = tid; q < T_ * C_ * 4; q += 192) {
            int j2 = q & 3;                 // pair index: n offset = 2*j2
            int o  = (q >> 2) % C_;
            int t  = q / (4 * C_);
            float2 y;
            y.x = stage[(t * 8 + 2 * j2) * C_ + o];
            y.y = stage[(t * 8 + 2 * j2 + 1) * C_ + o];
            *(float2*)(out + (((size_t)t * B_ + b) * C_ + o) * (size_t)N_ + n0 + g * 8 + 2 * j2) = y;
        }
        __syncthreads();
    }
}

// ---------------- launch ----------------
extern "C" void kernel_launch(void* const* d_in, const int* in_sizes, int n_in,
                              void* d_out, int out_size) {
    const float*         x  = (const float*)d_in[0];
    const unsigned char* ak = (const unsigned char*)d_in[1];
    const unsigned char* av = (const unsigned char*)d_in[2];
    const float*         wq = (const float*)d_in[3];
    const float*         qg = (const float*)d_in[4];
    const float*         qb = (const float*)d_in[5];
    const float*         qm = (const float*)d_in[6];
    const float*         qv = (const float*)d_in[7];
    const float*         wp = (const float*)d_in[8];
    const float*         bp = (const float*)d_in[9];
    const float*         pg = (const float*)d_in[10];
    const float*         pb = (const float*)d_in[11];
    const float*         pm = (const float*)d_in[12];
    const float*         pv = (const float*)d_in[13];
    float* out = (float*)d_out;

    (void)in_sizes; (void)n_in; (void)out_size;

    cudaFuncSetAttribute(k_main, cudaFuncAttributeMaxDynamicSharedMemorySize, SM_TOTAL);

    k_prep<<<(C_ * C_ + 255) / 256, 256>>>(wq, wp);
    k_lif_pack<<<dim3(N_ / 128, C_ / 64, B_), 128>>>(x);
    k_main<<<B_ * 32, 192, SM_TOTAL>>>(ak, av, qg, qb, qm, qv, bp, pg, pb, pm, pv, out);
}

// round 8
// speedup vs baseline: 1.6309x; 1.6309x over previous
#include <cuda_runtime.h>
#include <cuda_bf16.h>
#include <cstdint>

#define T_ 4
#define B_ 16
#define C_ 384
#define N_ 1024
#define TB_STRIDE (B_*C_*N_)
#define CAP_ 48

// ---------------- scratch (device globals; no allocation) ----------------
__device__ unsigned int  g_mask[(size_t)T_*B_*N_*12];     // 3 MB channel masks
__device__ __align__(16) __nv_bfloat16 g_wqT[C_*C_];      // wqT[c][o] bf16
__device__ __align__(16) float         g_wpT[C_*C_];      // wpT[c][o] fp32
__device__ float g_qinv[C_], g_qadd[C_], g_pinv[C_], g_pc[C_];

// ---------------- K0: transpose weights + fold bn constants ----------------
__global__ void k_prep(const float* __restrict__ wq, const float* __restrict__ wp,
                       const float* __restrict__ qg, const float* __restrict__ qb,
                       const float* __restrict__ qm, const float* __restrict__ qv,
                       const float* __restrict__ pg, const float* __restrict__ pb,
                       const float* __restrict__ pm, const float* __restrict__ pv,
                       const float* __restrict__ bp) {
    int i = blockIdx.x * blockDim.x + threadIdx.x;
    if (i < C_ * C_) {
        int o = i / C_;
        int c = i - o * C_;
        g_wqT[c * C_ + o] = __float2bfloat16(wq[i]);
        g_wpT[c * C_ + o] = wp[i];
    }
    if (i < C_) {
        float iv = qg[i] / sqrtf(qv[i] + 1e-5f);
        g_qinv[i] = iv;
        g_qadd[i] = qb[i] - qm[i] * iv;
        float iv2 = pg[i] / sqrtf(pv[i] + 1e-5f);
        g_pinv[i] = iv2;
        g_pc[i]   = pb[i] - pm[i] * iv2 + bp[i] * iv2;
    }
}

// ---------------- K1: fused LIF(x) + bit-pack into channel masks ----------------
__global__ void __launch_bounds__(128) k_lif_pack(const float* __restrict__ x) {
    const int n  = blockIdx.x * 128 + threadIdx.x;
    const int c0 = blockIdx.y * 64;
    const int b  = blockIdx.z;

    unsigned m[T_][2];
#pragma unroll
    for (int t = 0; t < T_; t++) { m[t][0] = 0u; m[t][1] = 0u; }

#pragma unroll
    for (int w2 = 0; w2 < 2; w2++) {
#pragma unroll 8
        for (int k = 0; k < 32; k++) {
            int c = c0 + w2 * 32 + k;
            const float* px = x + ((size_t)b * C_ + c) * N_ + n;
            float v = 0.0f;
#pragma unroll
            for (int t = 0; t < T_; t++) {
                float xt = px[(size_t)t * TB_STRIDE];
                float h = v + (xt - v) * 0.5f;
                bool  s = (h >= 1.0f);
                v = s ? 0.0f : h;
                m[t][w2] |= (s ? 1u : 0u) << k;
            }
        }
    }

#pragma unroll
    for (int t = 0; t < T_; t++)
#pragma unroll
        for (int w2 = 0; w2 < 2; w2++)
            g_mask[(((size_t)t * B_ + b) * N_ + n) * 12 + blockIdx.y * 2 + w2] = m[t][w2];
}

// ---------------- K2: warp-per-n fused sparse pipeline, direct output ----------------
// block = (b, 8 n); 256 threads = 8 warps; warp w owns n = n0 + w.
// lane owns outputs o in [8l, 8l+8) and (lanes<16) [256+8l, 256+8l+8).
// dynamic smem: stage f32[4][8][384] (49152) | lists u16[8][4][CAP_] (3072) | qmaskS u32[8][4][12] (1536)
#define SM_STAGE  0
#define SM_LISTS  49152
#define SM_QMASK  (49152 + 3072)
#define SM_TOTAL  (SM_QMASK + 1536)

__global__ void __launch_bounds__(256) k_main(
    const unsigned char* __restrict__ ak, const unsigned char* __restrict__ av,
    float* __restrict__ out)
{
    extern __shared__ unsigned char smraw[];
    float*          stage  = (float*)(smraw + SM_STAGE);            // [t][j][o]
    unsigned short* lists  = (unsigned short*)(smraw + SM_LISTS);   // [warp][t][CAP_]
    unsigned int*   qmaskS = (unsigned int*)(smraw + SM_QMASK);     // [warp][t][12]

    const int bg   = blockIdx.x;
    const int n0   = (bg & 127) * 8;
    const int b    = bg >> 7;
    const int tid  = threadIdx.x;
    const int lane = tid & 31;
    const int warp = tid >> 5;
    const int lm   = lane & 15;

    // ---- cooperative mask load for all 8 n ----
    for (int i = tid; i < 8 * T_ * 12; i += 256) {
        int w = i / (T_ * 12);
        int r = i - w * (T_ * 12);
        int t = r / 12, wd = r - t * 12;
        qmaskS[i] = g_mask[(((size_t)t * B_ + b) * N_ + n0 + w) * 12 + wd];
    }
    __syncthreads();

    // ---- per-warp: decode own masks into compact lists ----
    int Kt[T_];
#pragma unroll
    for (int t = 0; t < T_; t++) {
        const unsigned int* mw = qmaskS + (warp * T_ + t) * 12;
        unsigned short* lst = lists + (warp * T_ + t) * CAP_;
        int base = 0;
#pragma unroll
        for (int w12 = 0; w12 < 12; w12++) {
            unsigned m = mw[w12];
            if (m & (1u << lane)) {
                int pos = base + __popc(m & ((1u << lane) - 1));
                if (pos < CAP_) lst[pos] = (unsigned short)(w12 * 32 + lane);
            }
            base += __popc(m);   // uniform across warp
        }
        Kt[t] = base;
    }
    __syncwarp();

    // ---- phase 1: sparse q accumulate, bf16x2 (acc[t][0..3]=o[8l..], acc[t][4..7]=o[256+8l..]) ----
    __nv_bfloat162 acc[T_][8];
#pragma unroll
    for (int t = 0; t < T_; t++)
#pragma unroll
        for (int j = 0; j < 8; j++) acc[t][j] = __float2bfloat162_rn(0.0f);

#pragma unroll
    for (int t = 0; t < T_; t++) {
        const int K = Kt[t];
        const unsigned short* lst = lists + (warp * T_ + t) * CAP_;
        if (K <= CAP_) {
            for (int i = 0; i < K; i++) {
                const __nv_bfloat16* row = g_wqT + (int)lst[i] * C_;
                uint4 A0 = *(const uint4*)(row + 8 * lane);
                uint4 A1 = *(const uint4*)(row + 256 + 8 * lm);   // upper lanes mirror (harmless)
                const __nv_bfloat162* p0 = (const __nv_bfloat162*)&A0;
                const __nv_bfloat162* p1 = (const __nv_bfloat162*)&A1;
#pragma unroll
                for (int j = 0; j < 4; j++) acc[t][j]     = __hadd2(acc[t][j],     p0[j]);
#pragma unroll
                for (int j = 0; j < 4; j++) acc[t][4 + j] = __hadd2(acc[t][4 + j], p1[j]);
            }
        } else {
            const unsigned int* mw = qmaskS + (warp * T_ + t) * 12;
#pragma unroll
            for (int w12 = 0; w12 < 12; w12++) {
                unsigned m = mw[w12];
                while (m) {
                    int bit = __ffs((int)m) - 1;
                    m &= m - 1;
                    const __nv_bfloat16* row = g_wqT + (w12 * 32 + bit) * C_;
                    uint4 A0 = *(const uint4*)(row + 8 * lane);
                    uint4 A1 = *(const uint4*)(row + 256 + 8 * lm);
                    const __nv_bfloat162* p0 = (const __nv_bfloat162*)&A0;
                    const __nv_bfloat162* p1 = (const __nv_bfloat162*)&A1;
#pragma unroll
                    for (int j = 0; j < 4; j++) acc[t][j]     = __hadd2(acc[t][j],     p0[j]);
#pragma unroll
                    for (int j = 0; j < 4; j++) acc[t][4 + j] = __hadd2(acc[t][4 + j], p1[j]);
                }
            }
        }
    }

    // ---- phase 2: q_bn -> q_lif scan over t -> attn AND (lazy) -> rmask bits ----
    const int n = n0 + warp;
    unsigned rmask[T_] = {0u, 0u, 0u, 0u};
#pragma unroll
    for (int k = 0; k < 2; k++) {
        if (k == 0 || lane < 16) {
            const int obase = k * 256 + 8 * lane;   // for k=1, lane<16 so 8*lane==8*lm
#pragma unroll
            for (int jj = 0; jj < 8; jj++) {
                const int o = obase + jj;
                const float qi = g_qinv[o];
                const float qa = g_qadd[o];
                float v = 0.0f;
#pragma unroll
                for (int t = 0; t < T_; t++) {
                    __nv_bfloat162 pr = acc[t][k * 4 + (jj >> 1)];
                    float qf = (jj & 1) ? __high2float(pr) : __low2float(pr);
                    float qn = qf * qi + qa;
                    float h = v + (qn - v) * 0.5f;
                    bool s = (h >= 1.0f);
                    v = s ? 0.0f : h;
                    if (s) {
                        size_t idx = (((size_t)t * B_ + b) * C_ + o) * (size_t)N_ + n;
                        if (ak[idx] && av[idx]) rmask[t] |= 1u << (k * 8 + jj);
                    }
                }
            }
        }
    }

    // ---- phase 3 + epilogue per t: proj accumulate (usually skipped), bn, stage ----
#pragma unroll 1
    for (int t = 0; t < T_; t++) {
        float oa[16];
#pragma unroll
        for (int j = 0; j < 16; j++) oa[j] = 0.0f;

        if (__any_sync(0xffffffffu, rmask[t] != 0u)) {
#pragma unroll 1
            for (int wbit = 0; wbit < 16; wbit++) {
                unsigned mb = __ballot_sync(0xffffffffu, (rmask[t] >> wbit) & 1u);
                const int kk = wbit >> 3, jj = wbit & 7;
                while (mb) {
                    int l2 = __ffs((int)mb) - 1;
                    mb &= mb - 1;
                    int c = kk * 256 + 8 * l2 + jj;
                    const float* row = g_wpT + c * C_;
                    float4 w0 = *(const float4*)(row + 8 * lane);
                    float4 w1 = *(const float4*)(row + 8 * lane + 4);
                    float4 w2 = *(const float4*)(row + 256 + 8 * lm);
                    float4 w3 = *(const float4*)(row + 256 + 8 * lm + 4);
                    oa[0] += w0.x; oa[1] += w0.y; oa[2] += w0.z; oa[3] += w0.w;
                    oa[4] += w1.x; oa[5] += w1.y; oa[6] += w1.z; oa[7] += w1.w;
                    oa[8]  += w2.x; oa[9]  += w2.y; oa[10] += w2.z; oa[11] += w2.w;
                    oa[12] += w3.x; oa[13] += w3.y; oa[14] += w3.z; oa[15] += w3.w;
                }
            }
        }

        // epilogue: y = oa*pinv + pc, staged as [t][j=warp][o]
        {
            float4 y0, y1;
            const int o0 = 8 * lane;
            y0.x = oa[0] * g_pinv[o0+0] + g_pc[o0+0];
            y0.y = oa[1] * g_pinv[o0+1] + g_pc[o0+1];
            y0.z = oa[2] * g_pinv[o0+2] + g_pc[o0+2];
            y0.w = oa[3] * g_pinv[o0+3] + g_pc[o0+3];
            y1.x = oa[4] * g_pinv[o0+4] + g_pc[o0+4];
            y1.y = oa[5] * g_pinv[o0+5] + g_pc[o0+5];
            y1.z = oa[6] * g_pinv[o0+6] + g_pc[o0+6];
            y1.w = oa[7] * g_pinv[o0+7] + g_pc[o0+7];
            float* sp = stage + ((t * 8 + warp) * C_) + o0;
            *(float4*)sp = y0;
            *(float4*)(sp + 4) = y1;
            if (lane < 16) {
                const int o1 = 256 + 8 * lane;
                float4 z0, z1;
                z0.x = oa[8]  * g_pinv[o1+0] + g_pc[o1+0];
                z0.y = oa[9]  * g_pinv[o1+1] + g_pc[o1+1];
                z0.z = oa[10] * g_pinv[o1+2] + g_pc[o1+2];
                z0.w = oa[11] * g_pinv[o1+3] + g_pc[o1+3];
                z1.x = oa[12] * g_pinv[o1+4] + g_pc[o1+4];
                z1.y = oa[13] * g_pinv[o1+5] + g_pc[o1+5];
                z1.z = oa[14] * g_pinv[o1+6] + g_pc[o1+6];
                z1.w = oa[15] * g_pinv[o1+7] + g_pc[o1+7];
                float* sp1 = stage + ((t * 8 + warp) * C_) + o1;
                *(float4*)sp1 = z0;
                *(float4*)(sp1 + 4) = z1;
            }
        }
    }

    // ---- flush: [t][j][o] -> out[t][b][o][n0..n0+8), 32B rows ----
    __syncthreads();
    for (int r = tid; r < T_ * C_; r += 256) {
        int t = r / C_, o = r - (r / C_) * C_;
        const float* sp = stage + t * 8 * C_ + o;
        float4 u, w;
        u.x = sp[0 * C_]; u.y = sp[1 * C_]; u.z = sp[2 * C_]; u.w = sp[3 * C_];
        w.x = sp[4 * C_]; w.y = sp[5 * C_]; w.z = sp[6 * C_]; w.w = sp[7 * C_];
        float* dst = out + (((size_t)t * B_ + b) * C_ + o) * (size_t)N_ + n0;
        *(float4*)dst = u;
        *(float4*)(dst + 4) = w;
    }
}

// ---------------- launch ----------------
extern "C" void kernel_launch(void* const* d_in, const int* in_sizes, int n_in,
                              void* d_out, int out_size) {
    const float*         x  = (const float*)d_in[0];
    const unsigned char* ak = (const unsigned char*)d_in[1];
    const unsigned char* av = (const unsigned char*)d_in[2];
    const float*         wq = (const float*)d_in[3];
    const float*         qg = (const float*)d_in[4];
    const float*         qb = (const float*)d_in[5];
    const float*         qm = (const float*)d_in[6];
    const float*         qv = (const float*)d_in[7];
    const float*         wp = (const float*)d_in[8];
    const float*         bp = (const float*)d_in[9];
    const float*         pg = (const float*)d_in[10];
    const float*         pb = (const float*)d_in[11];
    const float*         pm = (const float*)d_in[12];
    const float*         pv = (const float*)d_in[13];
    float* out = (float*)d_out;

    (void)in_sizes; (void)n_in; (void)out_size;

    static int smem_set = 0;
    if (!smem_set) {
        cudaFuncSetAttribute(k_main, cudaFuncAttributeMaxDynamicSharedMemorySize, SM_TOTAL);
        smem_set = 1;
    }

    k_prep<<<(C_ * C_ + 255) / 256, 256>>>(wq, wp, qg, qb, qm, qv, pg, pb, pm, pv, bp);
    k_lif_pack<<<dim3(N_ / 128, C_ / 64, B_), 128>>>(x);
    k_main<<<B_ * 128, 256, SM_TOTAL>>>(ak, av, out);
}

// round 9
// speedup vs baseline: 2.0511x; 1.2576x over previous
#include <cuda_runtime.h>
#include <cuda_bf16.h>
#include <cstdint>

#define T_ 4
#define B_ 16
#define C_ 384
#define N_ 1024
#define TB_STRIDE (B_*C_*N_)
#define CAP_ 48
#define WQ_ROW_BYTES 768   // 384 * bf16

// ---------------- scratch (device globals; no allocation) ----------------
__device__ unsigned int  g_mask[(size_t)T_*B_*N_*12];     // 3 MB channel masks
__device__ __align__(16) __nv_bfloat16 g_wqT[C_*C_];      // wqT[c][o] bf16
__device__ __align__(16) float         g_wpT[C_*C_];      // wpT[c][o] fp32
__device__ __align__(16) float g_qinv[C_];
__device__ __align__(16) float g_qadd[C_];
__device__ __align__(16) float g_pinv[C_];
__device__ __align__(16) float g_pc[C_];

// ---------------- K0: transpose weights + fold bn constants ----------------
__global__ void k_prep(const float* __restrict__ wq, const float* __restrict__ wp,
                       const float* __restrict__ qg, const float* __restrict__ qb,
                       const float* __restrict__ qm, const float* __restrict__ qv,
                       const float* __restrict__ pg, const float* __restrict__ pb,
                       const float* __restrict__ pm, const float* __restrict__ pv,
                       const float* __restrict__ bp) {
    int i = blockIdx.x * blockDim.x + threadIdx.x;
    if (i < C_ * C_) {
        int o = i / C_;
        int c = i - o * C_;
        g_wqT[c * C_ + o] = __float2bfloat16(wq[i]);
        g_wpT[c * C_ + o] = wp[i];
    }
    if (i < C_) {
        float iv = qg[i] / sqrtf(qv[i] + 1e-5f);
        g_qinv[i] = iv;
        g_qadd[i] = qb[i] - qm[i] * iv;
        float iv2 = pg[i] / sqrtf(pv[i] + 1e-5f);
        g_pinv[i] = iv2;
        g_pc[i]   = pb[i] - pm[i] * iv2 + bp[i] * iv2;
    }
}

// ---------------- K1: fused LIF(x) + bit-pack, float4 over n ----------------
// grid (N/512, C/32, B); block 128; thread owns 4 consecutive n, 32 channels, all t.
__global__ void __launch_bounds__(128) k_lif_pack(const float* __restrict__ x) {
    const int n0 = blockIdx.x * 512 + threadIdx.x * 4;
    const int c0 = blockIdx.y * 32;
    const int b  = blockIdx.z;

    unsigned m[T_][4];
#pragma unroll
    for (int t = 0; t < T_; t++)
#pragma unroll
        for (int j = 0; j < 4; j++) m[t][j] = 0u;

#pragma unroll 4
    for (int k = 0; k < 32; k++) {
        const float* px = x + ((size_t)b * C_ + c0 + k) * N_ + n0;
        float v0 = 0.f, v1 = 0.f, v2 = 0.f, v3 = 0.f;
#pragma unroll
        for (int t = 0; t < T_; t++) {
            float4 xt = *(const float4*)(px + (size_t)t * TB_STRIDE);
            float h0 = v0 + (xt.x - v0) * 0.5f;
            float h1 = v1 + (xt.y - v1) * 0.5f;
            float h2 = v2 + (xt.z - v2) * 0.5f;
            float h3 = v3 + (xt.w - v3) * 0.5f;
            bool s0 = h0 >= 1.0f, s1 = h1 >= 1.0f, s2 = h2 >= 1.0f, s3 = h3 >= 1.0f;
            v0 = s0 ? 0.f : h0;  v1 = s1 ? 0.f : h1;
            v2 = s2 ? 0.f : h2;  v3 = s3 ? 0.f : h3;
            m[t][0] |= (s0 ? 1u : 0u) << k;
            m[t][1] |= (s1 ? 1u : 0u) << k;
            m[t][2] |= (s2 ? 1u : 0u) << k;
            m[t][3] |= (s3 ? 1u : 0u) << k;
        }
    }

#pragma unroll
    for (int t = 0; t < T_; t++)
#pragma unroll
        for (int j = 0; j < 4; j++)
            g_mask[(((size_t)t * B_ + b) * N_ + n0 + j) * 12 + blockIdx.y] = m[t][j];
}

// ---------------- K2: warp-per-n fused sparse pipeline, per-t flush ----------------
// block = (b, 8 n); 256 threads = 8 warps; warp w owns n = n0 + w.
// lane owns o in [8l, 8l+8) and (lanes<16) [256+8l, 256+8l+8).
__global__ void __launch_bounds__(256) k_main(
    const unsigned char* __restrict__ ak, const unsigned char* __restrict__ av,
    float* __restrict__ out)
{
    __shared__ float        stage[8 * C_];            // [j=n_local][o], one t at a time
    __shared__ unsigned int lists[8 * T_ * CAP_];     // byte offsets c*768
    __shared__ unsigned int qmaskS[8 * T_ * 12];

    const int bg   = blockIdx.x;
    const int n0   = (bg & 127) * 8;
    const int b    = bg >> 7;
    const int tid  = threadIdx.x;
    const int lane = tid & 31;
    const int warp = tid >> 5;
    const int lm   = lane & 15;

    // ---- cooperative mask load for all 8 n ----
    for (int i = tid; i < 8 * T_ * 12; i += 256) {
        int w = i / (T_ * 12);
        int r = i - w * (T_ * 12);
        int t = r / 12, wd = r - t * 12;
        qmaskS[i] = g_mask[(((size_t)t * B_ + b) * N_ + n0 + w) * 12 + wd];
    }
    __syncthreads();

    // ---- per-warp decode: masks -> compact byte-offset lists ----
    int Kt[T_];
#pragma unroll
    for (int t = 0; t < T_; t++) {
        const unsigned int* mw = qmaskS + (warp * T_ + t) * 12;
        unsigned int* lst = lists + (warp * T_ + t) * CAP_;
        int base = 0;
#pragma unroll
        for (int w12 = 0; w12 < 12; w12++) {
            unsigned m = mw[w12];
            if (m & (1u << lane)) {
                int pos = base + __popc(m & ((1u << lane) - 1));
                if (pos < CAP_) lst[pos] = (unsigned)(w12 * 32 + lane) * WQ_ROW_BYTES;
            }
            base += __popc(m);
        }
        Kt[t] = base;
    }
    __syncwarp();

    // ---- phase 1: sparse q accumulate in bf16x2 ----
    const char* wq_lo = (const char*)g_wqT + 16 * lane;        // o = 8l..8l+7
    const char* wq_hi = (const char*)g_wqT + 512 + 16 * lm;    // o = 256+8lm..

    __nv_bfloat162 acc[T_][8];
#pragma unroll
    for (int t = 0; t < T_; t++)
#pragma unroll
        for (int j = 0; j < 8; j++) acc[t][j] = __float2bfloat162_rn(0.0f);

#pragma unroll
    for (int t = 0; t < T_; t++) {
        const int K = Kt[t];
        const unsigned int* lst = lists + (warp * T_ + t) * CAP_;
        if (K <= CAP_) {
            int i = 0;
            for (; i + 2 <= K; i += 2) {
                unsigned off0 = lst[i], off1 = lst[i + 1];
                uint4 A0 = *(const uint4*)(wq_lo + off0);
                uint4 B0 = *(const uint4*)(wq_hi + off0);
                uint4 A1 = *(const uint4*)(wq_lo + off1);
                uint4 B1 = *(const uint4*)(wq_hi + off1);
                const __nv_bfloat162* a0 = (const __nv_bfloat162*)&A0;
                const __nv_bfloat162* b0 = (const __nv_bfloat162*)&B0;
                const __nv_bfloat162* a1 = (const __nv_bfloat162*)&A1;
                const __nv_bfloat162* b1 = (const __nv_bfloat162*)&B1;
#pragma unroll
                for (int j = 0; j < 4; j++) {
                    acc[t][j]     = __hadd2(__hadd2(acc[t][j],     a0[j]), a1[j]);
                    acc[t][4 + j] = __hadd2(__hadd2(acc[t][4 + j], b0[j]), b1[j]);
                }
            }
            if (i < K) {
                unsigned off = lst[i];
                uint4 A0 = *(const uint4*)(wq_lo + off);
                uint4 B0 = *(const uint4*)(wq_hi + off);
                const __nv_bfloat162* a0 = (const __nv_bfloat162*)&A0;
                const __nv_bfloat162* b0 = (const __nv_bfloat162*)&B0;
#pragma unroll
                for (int j = 0; j < 4; j++) {
                    acc[t][j]     = __hadd2(acc[t][j],     a0[j]);
                    acc[t][4 + j] = __hadd2(acc[t][4 + j], b0[j]);
                }
            }
        } else {
            // exact fallback: ffs scan of mask words
            const unsigned int* mw = qmaskS + (warp * T_ + t) * 12;
#pragma unroll
            for (int w12 = 0; w12 < 12; w12++) {
                unsigned m = mw[w12];
                while (m) {
                    int bit = __ffs((int)m) - 1;
                    m &= m - 1;
                    unsigned off = (unsigned)(w12 * 32 + bit) * WQ_ROW_BYTES;
                    uint4 A0 = *(const uint4*)(wq_lo + off);
                    uint4 B0 = *(const uint4*)(wq_hi + off);
                    const __nv_bfloat162* a0 = (const __nv_bfloat162*)&A0;
                    const __nv_bfloat162* b0 = (const __nv_bfloat162*)&B0;
#pragma unroll
                    for (int j = 0; j < 4; j++) {
                        acc[t][j]     = __hadd2(acc[t][j],     a0[j]);
                        acc[t][4 + j] = __hadd2(acc[t][4 + j], b0[j]);
                    }
                }
            }
        }
    }

    // ---- phase 2: q_bn -> q_lif scan -> attn AND (lazy) -> rmask ----
    const int n = n0 + warp;
    unsigned rmask[T_] = {0u, 0u, 0u, 0u};
    {
        // lower 8 outputs: vectorized constants
        float qiL[8], qaL[8];
        *(float4*)(qiL)     = *(const float4*)(g_qinv + 8 * lane);
        *(float4*)(qiL + 4) = *(const float4*)(g_qinv + 8 * lane + 4);
        *(float4*)(qaL)     = *(const float4*)(g_qadd + 8 * lane);
        *(float4*)(qaL + 4) = *(const float4*)(g_qadd + 8 * lane + 4);
#pragma unroll
        for (int jj = 0; jj < 8; jj++) {
            const int o = 8 * lane + jj;
            float v = 0.0f;
#pragma unroll
            for (int t = 0; t < T_; t++) {
                __nv_bfloat162 pr = acc[t][jj >> 1];
                float qf = (jj & 1) ? __high2float(pr) : __low2float(pr);
                float qn = qf * qiL[jj] + qaL[jj];
                float h = v + (qn - v) * 0.5f;
                bool s = (h >= 1.0f);
                v = s ? 0.0f : h;
                if (s) {
                    size_t idx = (((size_t)t * B_ + b) * C_ + o) * (size_t)N_ + n;
                    if (ak[idx] && av[idx]) rmask[t] |= 1u << jj;
                }
            }
        }
        if (lane < 16) {
            float qiU[8], qaU[8];
            *(float4*)(qiU)     = *(const float4*)(g_qinv + 256 + 8 * lane);
            *(float4*)(qiU + 4) = *(const float4*)(g_qinv + 256 + 8 * lane + 4);
            *(float4*)(qaU)     = *(const float4*)(g_qadd + 256 + 8 * lane);
            *(float4*)(qaU + 4) = *(const float4*)(g_qadd + 256 + 8 * lane + 4);
#pragma unroll
            for (int jj = 0; jj < 8; jj++) {
                const int o = 256 + 8 * lane + jj;
                float v = 0.0f;
#pragma unroll
                for (int t = 0; t < T_; t++) {
                    __nv_bfloat162 pr = acc[t][4 + (jj >> 1)];
                    float qf = (jj & 1) ? __high2float(pr) : __low2float(pr);
                    float qn = qf * qiU[jj] + qaU[jj];
                    float h = v + (qn - v) * 0.5f;
                    bool s = (h >= 1.0f);
                    v = s ? 0.0f : h;
                    if (s) {
                        size_t idx = (((size_t)t * B_ + b) * C_ + o) * (size_t)N_ + n;
                        if (ak[idx] && av[idx]) rmask[t] |= 1u << (8 + jj);
                    }
                }
            }
        }
    }

    // ---- per t: phase 3 (usually skipped), epilogue bn, stage, flush ----
#pragma unroll 1
    for (int t = 0; t < T_; t++) {
        float oa[16];
#pragma unroll
        for (int j = 0; j < 16; j++) oa[j] = 0.0f;

        if (__any_sync(0xffffffffu, rmask[t] != 0u)) {
#pragma unroll 1
            for (int wbit = 0; wbit < 16; wbit++) {
                unsigned mb = __ballot_sync(0xffffffffu, (rmask[t] >> wbit) & 1u);
                const int kk = wbit >> 3, jj = wbit & 7;
                while (mb) {
                    int l2 = __ffs((int)mb) - 1;
                    mb &= mb - 1;
                    int c = kk * 256 + 8 * l2 + jj;
                    const float* row = g_wpT + c * C_;
                    float4 w0 = *(const float4*)(row + 8 * lane);
                    float4 w1 = *(const float4*)(row + 8 * lane + 4);
                    float4 w2 = *(const float4*)(row + 256 + 8 * lm);
                    float4 w3 = *(const float4*)(row + 256 + 8 * lm + 4);
                    oa[0] += w0.x; oa[1] += w0.y; oa[2] += w0.z; oa[3] += w0.w;
                    oa[4] += w1.x; oa[5] += w1.y; oa[6] += w1.z; oa[7] += w1.w;
                    oa[8]  += w2.x; oa[9]  += w2.y; oa[10] += w2.z; oa[11] += w2.w;
                    oa[12] += w3.x; oa[13] += w3.y; oa[14] += w3.z; oa[15] += w3.w;
                }
            }
        }

        // epilogue: y = oa*pinv + pc  (vectorized constants), stage[j=warp][o]
        {
            const int o0 = 8 * lane;
            float4 piA = *(const float4*)(g_pinv + o0);
            float4 piB = *(const float4*)(g_pinv + o0 + 4);
            float4 pcA = *(const float4*)(g_pc + o0);
            float4 pcB = *(const float4*)(g_pc + o0 + 4);
            float4 y0, y1;
            y0.x = oa[0] * piA.x + pcA.x;  y0.y = oa[1] * piA.y + pcA.y;
            y0.z = oa[2] * piA.z + pcA.z;  y0.w = oa[3] * piA.w + pcA.w;
            y1.x = oa[4] * piB.x + pcB.x;  y1.y = oa[5] * piB.y + pcB.y;
            y1.z = oa[6] * piB.z + pcB.z;  y1.w = oa[7] * piB.w + pcB.w;
            float* sp = stage + warp * C_ + o0;
            *(float4*)sp = y0;
            *(float4*)(sp + 4) = y1;
            if (lane < 16) {
                const int o1 = 256 + 8 * lane;
                float4 piC = *(const float4*)(g_pinv + o1);
                float4 piD = *(const float4*)(g_pinv + o1 + 4);
                float4 pcC = *(const float4*)(g_pc + o1);
                float4 pcD = *(const float4*)(g_pc + o1 + 4);
                float4 z0, z1;
                z0.x = oa[8]  * piC.x + pcC.x;  z0.y = oa[9]  * piC.y + pcC.y;
                z0.z = oa[10] * piC.z + pcC.z;  z0.w = oa[11] * piC.w + pcC.w;
                z1.x = oa[12] * piD.x + pcD.x;  z1.y = oa[13] * piD.y + pcD.y;
                z1.z = oa[14] * piD.z + pcD.z;  z1.w = oa[15] * piD.w + pcD.w;
                float* sp1 = stage + warp * C_ + o1;
                *(float4*)sp1 = z0;
                *(float4*)(sp1 + 4) = z1;
            }
        }

        // flush t: stage[j][o] -> out[t][b][o][n0..n0+8)
        __syncthreads();
        for (int o = tid; o < C_; o += 256) {
            const float* sp = stage + o;
            float4 u, w;
            u.x = sp[0 * C_]; u.y = sp[1 * C_]; u.z = sp[2 * C_]; u.w = sp[3 * C_];
            w.x = sp[4 * C_]; w.y = sp[5 * C_]; w.z = sp[6 * C_]; w.w = sp[7 * C_];
            float* dst = out + (((size_t)t * B_ + b) * C_ + o) * (size_t)N_ + n0;
            *(float4*)dst = u;
            *(float4*)(dst + 4) = w;
        }
        __syncthreads();
    }
}

// ---------------- launch ----------------
extern "C" void kernel_launch(void* const* d_in, const int* in_sizes, int n_in,
                              void* d_out, int out_size) {
    const float*         x  = (const float*)d_in[0];
    const unsigned char* ak = (const unsigned char*)d_in[1];
    const unsigned char* av = (const unsigned char*)d_in[2];
    const float*         wq = (const float*)d_in[3];
    const float*         qg = (const float*)d_in[4];
    const float*         qb = (const float*)d_in[5];
    const float*         qm = (const float*)d_in[6];
    const float*         qv = (const float*)d_in[7];
    const float*         wp = (const float*)d_in[8];
    const float*         bp = (const float*)d_in[9];
    const float*         pg = (const float*)d_in[10];
    const float*         pb = (const float*)d_in[11];
    const float*         pm = (const float*)d_in[12];
    const float*         pv = (const float*)d_in[13];
    float* out = (float*)d_out;

    (void)in_sizes; (void)n_in; (void)out_size;

    k_prep<<<(C_ * C_ + 255) / 256, 256>>>(wq, wp, qg, qb, qm, qv, pg, pb, pm, pv, bp);
    k_lif_pack<<<dim3(N_ / 512, C_ / 32, B_), 128>>>(x);
    k_main<<<B_ * 128, 256>>>(ak, av, out);
}

// round 10
// speedup vs baseline: 2.2578x; 1.1008x over previous
#include <cuda_runtime.h>
#include <cuda_bf16.h>
#include <cstdint>

#define T_ 4
#define B_ 16
#define C_ 384
#define N_ 1024
#define TB_STRIDE (B_*C_*N_)
#define CAP_ 48
#define WQ_ROW_BYTES 768   // 384 * bf16

// ---------------- scratch (device globals; no allocation) ----------------
__device__ unsigned int  g_mask[(size_t)T_*B_*N_*12];     // 3 MB channel masks
__device__ __align__(16) __nv_bfloat16 g_wqT[C_*C_];      // wqT[c][o] bf16
__device__ __align__(16) float         g_wpT[C_*C_];      // wpT[c][o] fp32
__device__ __align__(16) float g_qinv[C_];
__device__ __align__(16) float g_qadd[C_];
__device__ __align__(16) float g_pinv[C_];
__device__ __align__(16) float g_pc[C_];

// ---------------- K0+K1 merged: LIF-pack blocks (0..383) + weight-prep blocks (384..1535) ----------------
#define LP_BLOCKS 384          // (N/512=2) * (C/32=12) * B=16
#define PREP_BLOCKS 1152       // C*C / 128

__global__ void __launch_bounds__(128) k_front(
    const float* __restrict__ x,
    const float* __restrict__ wq, const float* __restrict__ wp,
    const float* __restrict__ qg, const float* __restrict__ qb,
    const float* __restrict__ qm, const float* __restrict__ qv,
    const float* __restrict__ pg, const float* __restrict__ pb,
    const float* __restrict__ pm, const float* __restrict__ pv,
    const float* __restrict__ bp)
{
    const int bx = blockIdx.x;
    if (bx < LP_BLOCKS) {
        // ---- LIF(x) + bit-pack: thread owns 4 consecutive n, 32 channels, all t ----
        const int nx = bx & 1;
        const int cy = (bx >> 1) % 12;
        const int b  = bx / 24;
        const int n0 = nx * 512 + threadIdx.x * 4;
        const int c0 = cy * 32;

        unsigned m[T_][4];
#pragma unroll
        for (int t = 0; t < T_; t++)
#pragma unroll
            for (int j = 0; j < 4; j++) m[t][j] = 0u;

#pragma unroll 4
        for (int k = 0; k < 32; k++) {
            const float* px = x + ((size_t)b * C_ + c0 + k) * N_ + n0;
            float v0 = 0.f, v1 = 0.f, v2 = 0.f, v3 = 0.f;
#pragma unroll
            for (int t = 0; t < T_; t++) {
                float4 xt = *(const float4*)(px + (size_t)t * TB_STRIDE);
                float h0 = v0 + (xt.x - v0) * 0.5f;
                float h1 = v1 + (xt.y - v1) * 0.5f;
                float h2 = v2 + (xt.z - v2) * 0.5f;
                float h3 = v3 + (xt.w - v3) * 0.5f;
                bool s0 = h0 >= 1.0f, s1 = h1 >= 1.0f, s2 = h2 >= 1.0f, s3 = h3 >= 1.0f;
                v0 = s0 ? 0.f : h0;  v1 = s1 ? 0.f : h1;
                v2 = s2 ? 0.f : h2;  v3 = s3 ? 0.f : h3;
                m[t][0] |= (s0 ? 1u : 0u) << k;
                m[t][1] |= (s1 ? 1u : 0u) << k;
                m[t][2] |= (s2 ? 1u : 0u) << k;
                m[t][3] |= (s3 ? 1u : 0u) << k;
            }
        }

#pragma unroll
        for (int t = 0; t < T_; t++)
#pragma unroll
            for (int j = 0; j < 4; j++)
                g_mask[(((size_t)t * B_ + b) * N_ + n0 + j) * 12 + cy] = m[t][j];
    } else {
        // ---- weight transpose + bn constant folding ----
        int i = (bx - LP_BLOCKS) * 128 + threadIdx.x;
        if (i < C_ * C_) {
            int o = i / C_;
            int c = i - o * C_;
            g_wqT[c * C_ + o] = __float2bfloat16(wq[i]);
            g_wpT[c * C_ + o] = wp[i];
        }
        if (i < C_) {
            float iv = qg[i] / sqrtf(qv[i] + 1e-5f);
            g_qinv[i] = iv;
            g_qadd[i] = qb[i] - qm[i] * iv;
            float iv2 = pg[i] / sqrtf(pv[i] + 1e-5f);
            g_pinv[i] = iv2;
            g_pc[i]   = pb[i] - pm[i] * iv2 + bp[i] * iv2;
        }
    }
}

// ---------------- K2: warp-per-n fused sparse pipeline, per-t flush ----------------
// block = (b, 8 n); 256 threads = 8 warps; warp w owns n = n0 + w.
// lane owns o in [8l, 8l+8) and (lanes<16) [256+8l, 256+8l+8).
__global__ void __launch_bounds__(256) k_main(
    const unsigned char* __restrict__ ak, const unsigned char* __restrict__ av,
    float* __restrict__ out)
{
    __shared__ float        stage[8 * C_];            // [j=n_local][o], one t at a time
    __shared__ unsigned int lists[8 * T_ * CAP_];     // byte offsets c*768
    __shared__ unsigned int qmaskS[8 * T_ * 12];

    const int bg   = blockIdx.x;
    const int n0   = (bg & 127) * 8;
    const int b    = bg >> 7;
    const int tid  = threadIdx.x;
    const int lane = tid & 31;
    const int warp = tid >> 5;
    const int lm   = lane & 15;

    // ---- cooperative mask load for all 8 n ----
    for (int i = tid; i < 8 * T_ * 12; i += 256) {
        int w = i / (T_ * 12);
        int r = i - w * (T_ * 12);
        int t = r / 12, wd = r - t * 12;
        qmaskS[i] = g_mask[(((size_t)t * B_ + b) * N_ + n0 + w) * 12 + wd];
    }
    __syncthreads();

    // ---- per-warp decode: masks -> compact byte-offset lists ----
    int Kt[T_];
#pragma unroll
    for (int t = 0; t < T_; t++) {
        const unsigned int* mw = qmaskS + (warp * T_ + t) * 12;
        unsigned int* lst = lists + (warp * T_ + t) * CAP_;
        int base = 0;
#pragma unroll
        for (int w12 = 0; w12 < 12; w12++) {
            unsigned m = mw[w12];
            if (m & (1u << lane)) {
                int pos = base + __popc(m & ((1u << lane) - 1));
                if (pos < CAP_) lst[pos] = (unsigned)(w12 * 32 + lane) * WQ_ROW_BYTES;
            }
            base += __popc(m);
        }
        Kt[t] = base;
    }
    __syncwarp();

    // ---- phase 1: sparse q accumulate in bf16x2, unroll 4 ----
    const char* wq_lo = (const char*)g_wqT + 16 * lane;        // o = 8l..8l+7
    const char* wq_hi = (const char*)g_wqT + 512 + 16 * lm;    // o = 256+8lm..

    __nv_bfloat162 acc[T_][8];
#pragma unroll
    for (int t = 0; t < T_; t++)
#pragma unroll
        for (int j = 0; j < 8; j++) acc[t][j] = __float2bfloat162_rn(0.0f);

#pragma unroll
    for (int t = 0; t < T_; t++) {
        const int K = Kt[t];
        const unsigned int* lst = lists + (warp * T_ + t) * CAP_;
        if (K <= CAP_) {
            int i = 0;
            for (; i + 4 <= K; i += 4) {
                unsigned f0 = lst[i], f1 = lst[i + 1], f2 = lst[i + 2], f3 = lst[i + 3];
                uint4 A0 = *(const uint4*)(wq_lo + f0);
                uint4 A1 = *(const uint4*)(wq_lo + f1);
                uint4 A2 = *(const uint4*)(wq_lo + f2);
                uint4 A3 = *(const uint4*)(wq_lo + f3);
                uint4 B0 = *(const uint4*)(wq_hi + f0);
                uint4 B1 = *(const uint4*)(wq_hi + f1);
                uint4 B2 = *(const uint4*)(wq_hi + f2);
                uint4 B3 = *(const uint4*)(wq_hi + f3);
                const __nv_bfloat162* a0 = (const __nv_bfloat162*)&A0;
                const __nv_bfloat162* a1 = (const __nv_bfloat162*)&A1;
                const __nv_bfloat162* a2 = (const __nv_bfloat162*)&A2;
                const __nv_bfloat162* a3 = (const __nv_bfloat162*)&A3;
                const __nv_bfloat162* b0 = (const __nv_bfloat162*)&B0;
                const __nv_bfloat162* b1 = (const __nv_bfloat162*)&B1;
                const __nv_bfloat162* b2 = (const __nv_bfloat162*)&B2;
                const __nv_bfloat162* b3 = (const __nv_bfloat162*)&B3;
#pragma unroll
                for (int j = 0; j < 4; j++) {
                    __nv_bfloat162 u = __hadd2(__hadd2(a0[j], a1[j]), __hadd2(a2[j], a3[j]));
                    acc[t][j] = __hadd2(acc[t][j], u);
                    __nv_bfloat162 w = __hadd2(__hadd2(b0[j], b1[j]), __hadd2(b2[j], b3[j]));
                    acc[t][4 + j] = __hadd2(acc[t][4 + j], w);
                }
            }
            for (; i < K; i++) {
                unsigned off = lst[i];
                uint4 A0 = *(const uint4*)(wq_lo + off);
                uint4 B0 = *(const uint4*)(wq_hi + off);
                const __nv_bfloat162* a0 = (const __nv_bfloat162*)&A0;
                const __nv_bfloat162* b0 = (const __nv_bfloat162*)&B0;
#pragma unroll
                for (int j = 0; j < 4; j++) {
                    acc[t][j]     = __hadd2(acc[t][j],     a0[j]);
                    acc[t][4 + j] = __hadd2(acc[t][4 + j], b0[j]);
                }
            }
        } else {
            // exact fallback: ffs scan of mask words
            const unsigned int* mw = qmaskS + (warp * T_ + t) * 12;
#pragma unroll
            for (int w12 = 0; w12 < 12; w12++) {
                unsigned m = mw[w12];
                while (m) {
                    int bit = __ffs((int)m) - 1;
                    m &= m - 1;
                    unsigned off = (unsigned)(w12 * 32 + bit) * WQ_ROW_BYTES;
                    uint4 A0 = *(const uint4*)(wq_lo + off);
                    uint4 B0 = *(const uint4*)(wq_hi + off);
                    const __nv_bfloat162* a0 = (const __nv_bfloat162*)&A0;
                    const __nv_bfloat162* b0 = (const __nv_bfloat162*)&B0;
#pragma unroll
                    for (int j = 0; j < 4; j++) {
                        acc[t][j]     = __hadd2(acc[t][j],     a0[j]);
                        acc[t][4 + j] = __hadd2(acc[t][4 + j], b0[j]);
                    }
                }
            }
        }
    }

    // ---- phase 2a: branch-free q_bn -> q_lif scan -> 16-bit spike mask per lane ----
    const int n = n0 + warp;
    unsigned smask[T_] = {0u, 0u, 0u, 0u};
    {
        float qiL[8], qaL[8];
        *(float4*)(qiL)     = *(const float4*)(g_qinv + 8 * lane);
        *(float4*)(qiL + 4) = *(const float4*)(g_qinv + 8 * lane + 4);
        *(float4*)(qaL)     = *(const float4*)(g_qadd + 8 * lane);
        *(float4*)(qaL + 4) = *(const float4*)(g_qadd + 8 * lane + 4);
#pragma unroll
        for (int jj = 0; jj < 8; jj++) {
            float v = 0.0f;
#pragma unroll
            for (int t = 0; t < T_; t++) {
                __nv_bfloat162 pr = acc[t][jj >> 1];
                float qf = (jj & 1) ? __high2float(pr) : __low2float(pr);
                float qn = fmaf(qf, qiL[jj], qaL[jj]);
                float h = v + (qn - v) * 0.5f;
                bool s = (h >= 1.0f);
                v = s ? 0.0f : h;
                smask[t] |= (s ? 1u : 0u) << jj;
            }
        }
        if (lane < 16) {
            float qiU[8], qaU[8];
            *(float4*)(qiU)     = *(const float4*)(g_qinv + 256 + 8 * lane);
            *(float4*)(qiU + 4) = *(const float4*)(g_qinv + 256 + 8 * lane + 4);
            *(float4*)(qaU)     = *(const float4*)(g_qadd + 256 + 8 * lane);
            *(float4*)(qaU + 4) = *(const float4*)(g_qadd + 256 + 8 * lane + 4);
#pragma unroll
            for (int jj = 0; jj < 8; jj++) {
                float v = 0.0f;
#pragma unroll
                for (int t = 0; t < T_; t++) {
                    __nv_bfloat162 pr = acc[t][4 + (jj >> 1)];
                    float qf = (jj & 1) ? __high2float(pr) : __low2float(pr);
                    float qn = fmaf(qf, qiU[jj], qaU[jj]);
                    float h = v + (qn - v) * 0.5f;
                    bool s = (h >= 1.0f);
                    v = s ? 0.0f : h;
                    smask[t] |= (s ? 1u : 0u) << (8 + jj);
                }
            }
        }
    }

    // ---- phase 2b: attn AND, one guarded region per t ----
    unsigned rmask[T_];
#pragma unroll
    for (int t = 0; t < T_; t++) {
        rmask[t] = 0u;
        if (__any_sync(0xffffffffu, smask[t] != 0u)) {
            unsigned sm = smask[t];
            const size_t base_t = (((size_t)t * B_ + b) * C_) * (size_t)N_ + n;
            while (sm) {
                int j = __ffs((int)sm) - 1;
                sm &= sm - 1;
                int o = (j < 8) ? (8 * lane + j) : (256 + 8 * lane + j - 8);
                size_t idx = base_t + (size_t)o * N_;
                if (ak[idx] && av[idx]) rmask[t] |= 1u << j;
            }
        }
    }

    // ---- per t: phase 3 (usually skipped), epilogue bn, stage, flush ----
#pragma unroll 1
    for (int t = 0; t < T_; t++) {
        float oa[16];
#pragma unroll
        for (int j = 0; j < 16; j++) oa[j] = 0.0f;

        if (__any_sync(0xffffffffu, rmask[t] != 0u)) {
#pragma unroll 1
            for (int wbit = 0; wbit < 16; wbit++) {
                unsigned mb = __ballot_sync(0xffffffffu, (rmask[t] >> wbit) & 1u);
                const int kk = wbit >> 3, jj = wbit & 7;
                while (mb) {
                    int l2 = __ffs((int)mb) - 1;
                    mb &= mb - 1;
                    int c = kk * 256 + 8 * l2 + jj;
                    const float* row = g_wpT + c * C_;
                    float4 w0 = *(const float4*)(row + 8 * lane);
                    float4 w1 = *(const float4*)(row + 8 * lane + 4);
                    float4 w2 = *(const float4*)(row + 256 + 8 * lm);
                    float4 w3 = *(const float4*)(row + 256 + 8 * lm + 4);
                    oa[0] += w0.x; oa[1] += w0.y; oa[2] += w0.z; oa[3] += w0.w;
                    oa[4] += w1.x; oa[5] += w1.y; oa[6] += w1.z; oa[7] += w1.w;
                    oa[8]  += w2.x; oa[9]  += w2.y; oa[10] += w2.z; oa[11] += w2.w;
                    oa[12] += w3.x; oa[13] += w3.y; oa[14] += w3.z; oa[15] += w3.w;
                }
            }
        }

        // epilogue: y = oa*pinv + pc  (vectorized constants), stage[j=warp][o]
        {
            const int o0 = 8 * lane;
            float4 piA = *(const float4*)(g_pinv + o0);
            float4 piB = *(const float4*)(g_pinv + o0 + 4);
            float4 pcA = *(const float4*)(g_pc + o0);
            float4 pcB = *(const float4*)(g_pc + o0 + 4);
            float4 y0, y1;
            y0.x = oa[0] * piA.x + pcA.x;  y0.y = oa[1] * piA.y + pcA.y;
            y0.z = oa[2] * piA.z + pcA.z;  y0.w = oa[3] * piA.w + pcA.w;
            y1.x = oa[4] * piB.x + pcB.x;  y1.y = oa[5] * piB.y + pcB.y;
            y1.z = oa[6] * piB.z + pcB.z;  y1.w = oa[7] * piB.w + pcB.w;
            float* sp = stage + warp * C_ + o0;
            *(float4*)sp = y0;
            *(float4*)(sp + 4) = y1;
            if (lane < 16) {
                const int o1 = 256 + 8 * lane;
                float4 piC = *(const float4*)(g_pinv + o1);
                float4 piD = *(const float4*)(g_pinv + o1 + 4);
                float4 pcC = *(const float4*)(g_pc + o1);
                float4 pcD = *(const float4*)(g_pc + o1 + 4);
                float4 z0, z1;
                z0.x = oa[8]  * piC.x + pcC.x;  z0.y = oa[9]  * piC.y + pcC.y;
                z0.z = oa[10] * piC.z + pcC.z;  z0.w = oa[11] * piC.w + pcC.w;
                z1.x = oa[12] * piD.x + pcD.x;  z1.y = oa[13] * piD.y + pcD.y;
                z1.z = oa[14] * piD.z + pcD.z;  z1.w = oa[15] * piD.w + pcD.w;
                float* sp1 = stage + warp * C_ + o1;
                *(float4*)sp1 = z0;
                *(float4*)(sp1 + 4) = z1;
            }
        }

        // flush t: stage[j][o] -> out[t][b][o][n0..n0+8)
        __syncthreads();
        for (int o = tid; o < C_; o += 256) {
            const float* sp = stage + o;
            float4 u, w;
            u.x = sp[0 * C_]; u.y = sp[1 * C_]; u.z = sp[2 * C_]; u.w = sp[3 * C_];
            w.x = sp[4 * C_]; w.y = sp[5 * C_]; w.z = sp[6 * C_]; w.w = sp[7 * C_];
            float* dst = out + (((size_t)t * B_ + b) * C_ + o) * (size_t)N_ + n0;
            *(float4*)dst = u;
            *(float4*)(dst + 4) = w;
        }
        __syncthreads();
    }
}

// ---------------- launch ----------------
extern "C" void kernel_launch(void* const* d_in, const int* in_sizes, int n_in,
                              void* d_out, int out_size) {
    const float*         x  = (const float*)d_in[0];
    const unsigned char* ak = (const unsigned char*)d_in[1];
    const unsigned char* av = (const unsigned char*)d_in[2];
    const float*         wq = (const float*)d_in[3];
    const float*         qg = (const float*)d_in[4];
    const float*         qb = (const float*)d_in[5];
    const float*         qm = (const float*)d_in[6];
    const float*         qv = (const float*)d_in[7];
    const float*         wp = (const float*)d_in[8];
    const float*         bp = (const float*)d_in[9];
    const float*         pg = (const float*)d_in[10];
    const float*         pb = (const float*)d_in[11];
    const float*         pm = (const float*)d_in[12];
    const float*         pv = (const float*)d_in[13];
    float* out = (float*)d_out;

    (void)in_sizes; (void)n_in; (void)out_size;

    k_front<<<LP_BLOCKS + PREP_BLOCKS, 128>>>(x, wq, wp, qg, qb, qm, qv, pg, pb, pm, pv, bp);
    k_main<<<B_ * 128, 256>>>(ak, av, out);
}